// round 11
// baseline (speedup 1.0000x reference)
#include <cuda_runtime.h>
#include <cuda_bf16.h>
#include <cstdint>

#define SEQL 2048
#define DH 64
#define BQ 128
#define BK 128
#define NT 16

__device__ float g_rowsum[2 * 16 * SEQL];

#define K1_QH 0
#define K1_QL 18432
#define K1_KH 36864
#define K1_KL 55296
#define K1_MS 73728
#define K1_RS 90112
#define K1_FLG 90624
#define K1_TOT 90656
#define K2_PH 0
#define K2_PL 34816
#define K2_VH 69632
#define K2_VL 87040
#define K2_INV 104448
#define K2_TOT 104960

static __device__ __forceinline__ float fexp8(float x) {  // exp(x/8), FMA-pipe, clamped
    float t = x * 0.18033688011112042f;
    t = fminf(fmaxf(t, -126.0f), 126.0f);
    float kf = t + 12582912.0f;
    float f = t - (kf - 12582912.0f);
    int ki = __float_as_int(kf) << 23;
    float p = 1.3333558146e-3f;
    p = fmaf(p, f, 9.6181291076e-3f);
    p = fmaf(p, f, 5.55041086648e-2f);
    p = fmaf(p, f, 2.402265069591e-1f);
    p = fmaf(p, f, 6.931471805599e-1f);
    p = fmaf(p, f, 1.0f);
    return __int_as_float(__float_as_int(p) + ki);
}

static __device__ __forceinline__ void split2(float a, float b, uint32_t& hi, uint32_t& lo) {
    __nv_bfloat16 ha = __float2bfloat16_rn(a), hb = __float2bfloat16_rn(b);
    hi = (uint32_t)__bfloat16_as_ushort(ha) | ((uint32_t)__bfloat16_as_ushort(hb) << 16);
    lo = (uint32_t)__bfloat16_as_ushort(__float2bfloat16_rn(a - __bfloat162float(ha))) |
         ((uint32_t)__bfloat16_as_ushort(__float2bfloat16_rn(b - __bfloat162float(hb))) << 16);
}

static __device__ __forceinline__ void mma16816(float* c, const uint32_t* a, uint32_t b0, uint32_t b1) {
    asm volatile(
        "mma.sync.aligned.m16n8k16.row.col.f32.bf16.bf16.f32 "
        "{%0,%1,%2,%3}, {%4,%5,%6,%7}, {%8,%9}, {%0,%1,%2,%3};"
        : "+f"(c[0]), "+f"(c[1]), "+f"(c[2]), "+f"(c[3])
        : "r"(a[0]), "r"(a[1]), "r"(a[2]), "r"(a[3]), "r"(b0), "r"(b1));
}

static __device__ __forceinline__ void stage64(char* sm, int oh, int ol, const float* g, int tid) {
    for (int i = tid; i < 2048; i += 256) {
        int r = i >> 4, c = (i & 15) * 4;
        float4 x = __ldg((const float4*)(g + r * 64 + c));
        uint32_t h0, l0, h1, l1;
        split2(x.x, x.y, h0, l0); split2(x.z, x.w, h1, l1);
        *(uint2*)(sm + oh + r * 144 + c * 2) = make_uint2(h0, h1);
        *(uint2*)(sm + ol + r * 144 + c * 2) = make_uint2(l0, l1);
    }
}

__global__ void __launch_bounds__(256, 2)
k1_qk_exp(const float* __restrict__ q, const float* __restrict__ k,
          const unsigned char* __restrict__ mask, float* __restrict__ attn) {
    extern __shared__ char sm[];
    const int tid = threadIdx.x, lane = tid & 31, w = tid >> 5;
    const int g = lane >> 2, t4 = lane & 3, wm = w >> 1, wn = w & 1;
    const int qt = blockIdx.x, bh = blockIdx.y, b = bh >> 4, qb = qt * BQ;
    const float* qg = q + ((size_t)bh * SEQL + qb) * DH;
    const float* kg = k + (size_t)bh * SEQL * DH;
    const unsigned char* mg8 = mask + ((size_t)b * SEQL + qb) * SEQL;
    const uint32_t* mg32 = (const uint32_t*)mask + ((size_t)b * SEQL + qb) * SEQL;
    float* ag = attn + ((size_t)bh * SEQL + qb) * SEQL;
    float* rs = (float*)(sm + K1_RS);
    if (tid < 128) rs[tid] = 0.f;
    if (tid == 0) {  // mask dtype probe: any 32-bit word >1 => bool bytes, else int32
        const uint32_t* mw = (const uint32_t*)mask;
        uint32_t big = 0;
        for (int i = 0; i < 16; ++i) big |= (__ldg(mw + i) > 1u) ? 1u : 0u;
        *(int*)(sm + K1_FLG) = big ? 0 : 1;
    }
    stage64(sm, K1_QH, K1_QL, qg, tid);

    float rsum[4] = {0.f, 0.f, 0.f, 0.f};

    for (int t = 0; t < NT; ++t) {
        __syncthreads();
        stage64(sm, K1_KH, K1_KL, kg + (size_t)t * BK * DH, tid);
        if (*(const int*)(sm + K1_FLG)) {
            for (int i = tid; i < 4096; i += 256) {
                int r = i >> 5, c4 = (i & 31) * 4;
                uint4 wv = __ldg((const uint4*)(mg32 + (size_t)r * SEQL + t * BK + c4));
                *(uchar4*)(sm + K1_MS + r * 128 + c4) =
                    make_uchar4(wv.x != 0, wv.y != 0, wv.z != 0, wv.w != 0);
            }
        } else {
            for (int i = tid; i < 1024; i += 256) {
                int r = i >> 3, c = (i & 7) * 16;
                *(uint4*)(sm + K1_MS + r * 128 + c) =
                    __ldg((const uint4*)(mg8 + (size_t)r * SEQL + t * BK + c));
            }
        }
        __syncthreads();

        float acc[2][8][4];
#pragma unroll
        for (int mf = 0; mf < 2; ++mf)
#pragma unroll
            for (int nf = 0; nf < 8; ++nf)
#pragma unroll
                for (int e = 0; e < 4; ++e) acc[mf][nf][e] = 0.f;

#pragma unroll
        for (int ks = 0; ks < 4; ++ks) {
            uint32_t ah[2][4], al[2][4];
#pragma unroll
            for (int mf = 0; mf < 2; ++mf) {
                int rb = (wm * 32 + mf * 16 + g) * 144 + ks * 32 + t4 * 4;
                ah[mf][0] = *(uint32_t*)(sm + K1_QH + rb);
                ah[mf][1] = *(uint32_t*)(sm + K1_QH + rb + 8 * 144);
                ah[mf][2] = *(uint32_t*)(sm + K1_QH + rb + 16);
                ah[mf][3] = *(uint32_t*)(sm + K1_QH + rb + 8 * 144 + 16);
                al[mf][0] = *(uint32_t*)(sm + K1_QL + rb);
                al[mf][1] = *(uint32_t*)(sm + K1_QL + rb + 8 * 144);
                al[mf][2] = *(uint32_t*)(sm + K1_QL + rb + 16);
                al[mf][3] = *(uint32_t*)(sm + K1_QL + rb + 8 * 144 + 16);
            }
#pragma unroll
            for (int nf = 0; nf < 8; ++nf) {
                int cb = (wn * 64 + nf * 8 + g) * 144 + ks * 32 + t4 * 4;
                uint32_t bh0 = *(uint32_t*)(sm + K1_KH + cb), bh1 = *(uint32_t*)(sm + K1_KH + cb + 16);
                uint32_t bl0 = *(uint32_t*)(sm + K1_KL + cb), bl1 = *(uint32_t*)(sm + K1_KL + cb + 16);
#pragma unroll
                for (int mf = 0; mf < 2; ++mf) {
                    mma16816(acc[mf][nf], ah[mf], bh0, bh1);
                    mma16816(acc[mf][nf], ah[mf], bl0, bl1);
                    mma16816(acc[mf][nf], al[mf], bh0, bh1);
                }
            }
        }

#pragma unroll
        for (int mf = 0; mf < 2; ++mf)
#pragma unroll
            for (int nf = 0; nf < 8; ++nf) {
                int r0 = wm * 32 + mf * 16 + g, c0 = wn * 64 + nf * 8 + t4 * 2;
                unsigned m01 = *(unsigned short*)(sm + K1_MS + r0 * 128 + c0);
                unsigned m23 = *(unsigned short*)(sm + K1_MS + (r0 + 8) * 128 + c0);
                float e0 = (m01 & 0xffu) ? fexp8(acc[mf][nf][0]) : 1.0f;
                float e1 = (m01 >> 8)    ? fexp8(acc[mf][nf][1]) : 1.0f;
                float e2 = (m23 & 0xffu) ? fexp8(acc[mf][nf][2]) : 1.0f;
                float e3 = (m23 >> 8)    ? fexp8(acc[mf][nf][3]) : 1.0f;
                rsum[mf * 2] += e0 + e1;
                rsum[mf * 2 + 1] += e2 + e3;
                float* d = ag + (size_t)r0 * SEQL + t * BK + c0;
                *(float2*)d = make_float2(e0, e1);
                *(float2*)(d + 8 * SEQL) = make_float2(e2, e3);
            }
    }

#pragma unroll
    for (int i = 0; i < 4; ++i) {
        rsum[i] += __shfl_xor_sync(~0u, rsum[i], 1);
        rsum[i] += __shfl_xor_sync(~0u, rsum[i], 2);
    }
    if (t4 == 0) {
        atomicAdd(&rs[wm * 32 + g], rsum[0]);
        atomicAdd(&rs[wm * 32 + g + 8], rsum[1]);
        atomicAdd(&rs[wm * 32 + 16 + g], rsum[2]);
        atomicAdd(&rs[wm * 32 + 24 + g], rsum[3]);
    }
    __syncthreads();
    if (tid < 128) g_rowsum[(size_t)bh * SEQL + qb + tid] = rs[tid];
}

__global__ void __launch_bounds__(256, 2)
k2_norm_pv(const float* __restrict__ v, float* __restrict__ attn, float* __restrict__ ctx) {
    extern __shared__ char sm[];
    const int tid = threadIdx.x, lane = tid & 31, w = tid >> 5;
    const int g = lane >> 2, t4 = lane & 3, wm = w >> 1, wn = w & 1;
    const int qt = blockIdx.x, bh = blockIdx.y, qb = qt * BQ;
    float* ag = attn + ((size_t)bh * SEQL + qb) * SEQL;
    const float* vg = v + (size_t)bh * SEQL * DH;
    float* inv = (float*)(sm + K2_INV);
    if (tid < 128)
        inv[tid] = 1.0f / fmaxf(g_rowsum[(size_t)bh * SEQL + qb + tid], 1e-30f);

    float acc[2][4][4];
#pragma unroll
    for (int mf = 0; mf < 2; ++mf)
#pragma unroll
        for (int nf = 0; nf < 4; ++nf)
#pragma unroll
            for (int e = 0; e < 4; ++e) acc[mf][nf][e] = 0.f;

    for (int t = 0; t < NT; ++t) {
        __syncthreads();
        for (int i = tid; i < 4096; i += 256) {
            int r = i >> 5, c4 = (i & 31) * 4;
            float* p = ag + (size_t)r * SEQL + t * BK + c4;
            float4 e = *(float4*)p;
            float il = inv[r];
            e.x *= il; e.y *= il; e.z *= il; e.w *= il;
            *(float4*)p = e;
            uint32_t h0, l0, h1, l1;
            split2(e.x, e.y, h0, l0); split2(e.z, e.w, h1, l1);
            *(uint2*)(sm + K2_PH + r * 272 + c4 * 2) = make_uint2(h0, h1);
            *(uint2*)(sm + K2_PL + r * 272 + c4 * 2) = make_uint2(l0, l1);
        }
        for (int i = tid; i < 2048; i += 256) {
            int key = i >> 4, c4 = (i & 15) * 4;   // FIXED: 16 float4 per 64-dim key row
            float4 x = __ldg((const float4*)(vg + (size_t)(t * BK + key) * DH + c4));
            float xs[4] = {x.x, x.y, x.z, x.w};
#pragma unroll
            for (int j = 0; j < 4; ++j) {
                __nv_bfloat16 h = __float2bfloat16_rn(xs[j]);
                __nv_bfloat16 l = __float2bfloat16_rn(xs[j] - __bfloat162float(h));
                *(unsigned short*)(sm + K2_VH + (c4 + j) * 272 + key * 2) = __bfloat16_as_ushort(h);
                *(unsigned short*)(sm + K2_VL + (c4 + j) * 272 + key * 2) = __bfloat16_as_ushort(l);
            }
        }
        __syncthreads();

#pragma unroll
        for (int ks = 0; ks < 8; ++ks) {
            uint32_t ah[2][4], al[2][4];
#pragma unroll
            for (int mf = 0; mf < 2; ++mf) {
                int rb = (wm * 32 + mf * 16 + g) * 272 + ks * 32 + t4 * 4;
                ah[mf][0] = *(uint32_t*)(sm + K2_PH + rb);
                ah[mf][1] = *(uint32_t*)(sm + K2_PH + rb + 8 * 272);
                ah[mf][2] = *(uint32_t*)(sm + K2_PH + rb + 16);
                ah[mf][3] = *(uint32_t*)(sm + K2_PH + rb + 8 * 272 + 16);
                al[mf][0] = *(uint32_t*)(sm + K2_PL + rb);
                al[mf][1] = *(uint32_t*)(sm + K2_PL + rb + 8 * 272);
                al[mf][2] = *(uint32_t*)(sm + K2_PL + rb + 16);
                al[mf][3] = *(uint32_t*)(sm + K2_PL + rb + 8 * 272 + 16);
            }
#pragma unroll
            for (int nf = 0; nf < 4; ++nf) {
                int db = (wn * 32 + nf * 8 + g) * 272 + ks * 32 + t4 * 4;
                uint32_t bh0 = *(uint32_t*)(sm + K2_VH + db), bh1 = *(uint32_t*)(sm + K2_VH + db + 16);
                uint32_t bl0 = *(uint32_t*)(sm + K2_VL + db), bl1 = *(uint32_t*)(sm + K2_VL + db + 16);
#pragma unroll
                for (int mf = 0; mf < 2; ++mf) {
                    mma16816(acc[mf][nf], ah[mf], bh0, bh1);
                    mma16816(acc[mf][nf], ah[mf], bl0, bl1);
                    mma16816(acc[mf][nf], al[mf], bh0, bh1);
                }
            }
        }
    }
#pragma unroll
    for (int mf = 0; mf < 2; ++mf)
#pragma unroll
        for (int nf = 0; nf < 4; ++nf) {
            int r0 = qb + wm * 32 + mf * 16 + g, d0 = wn * 32 + nf * 8 + t4 * 2;
            float* o = ctx + ((size_t)bh * SEQL + r0) * DH + d0;
            *(float2*)o = make_float2(acc[mf][nf][0], acc[mf][nf][1]);
            *(float2*)(o + 8 * DH) = make_float2(acc[mf][nf][2], acc[mf][nf][3]);
        }
}

extern "C" void kernel_launch(void* const* d_in, const int* in_sizes, int n_in,
                              void* d_out, int out_size) {
    const float* q = (const float*)d_in[0];
    const float* k = (const float*)d_in[1];
    const float* v = (const float*)d_in[2];
    const unsigned char* mask = (const unsigned char*)d_in[3];
    float* out = (float*)d_out;
    float* out_ctx = out;
    float* out_attn = out + (size_t)2 * 16 * SEQL * DH;

    cudaFuncSetAttribute(k1_qk_exp, cudaFuncAttributeMaxDynamicSharedMemorySize, K1_TOT);
    cudaFuncSetAttribute(k2_norm_pv, cudaFuncAttributeMaxDynamicSharedMemorySize, K2_TOT);
    dim3 grid(SEQL / BQ, 32);
    k1_qk_exp<<<grid, 256, K1_TOT>>>(q, k, mask, out_attn);
    k2_norm_pv<<<grid, 256, K2_TOT>>>(v, out_attn, out_ctx);
}